// round 15
// baseline (speedup 1.0000x reference)
#include <cuda_runtime.h>
#include <cuda_bf16.h>
#include <cstdint>

#define BSZ   8
#define NROI  64
#define HDIM  512
#define NLAYER 5
#define BI    (BSZ*NROI)                     // 512 (b,i) pairs
#define NPAIR 2080                           // i<=j pairs
#define NPPAD 2112                           // 33*64 padded

// ---------------- scratch (device globals; no allocation allowed) ----------
// edge_state in FULL layout [b][i*64+j][o], mirror-written (symmetric).
__device__ __nv_bfloat16 g_ebuf[2][(size_t)BSZ*NROI*NROI*HDIM];
__device__ __nv_bfloat16 g_eW16[(size_t)NLAYER*HDIM*HDIM];  // bf16 edge weights
__device__ __nv_bfloat16 g_nW16[(size_t)NLAYER*HDIM*HDIM];  // bf16 node weights
__device__ __nv_bfloat16 g_ns16[BI*HDIM];               // bf16 mirror of node_state
__device__ float g_nm[BI*HDIM];
__device__ float g_ns[BI*HDIM];
__device__ float g_denom[BI];
__device__ float g_em0[BSZ*HDIM];                       // layer-0 edge matvec (incl. bias)
__device__ float g_e0[BSZ*HDIM];                        // mean of img_featmap
__device__ ushort2 g_pt[NPPAD];                         // pair p -> (i,j), i<=j

__device__ __forceinline__ float leaky(float x) { return x >= 0.f ? x : 0.01f * x; }
__device__ __forceinline__ unsigned smem_u32(const void* p) {
    return (unsigned)__cvta_generic_to_shared(p);
}
__device__ __forceinline__ void cpa16(unsigned dst, const void* src) {
    asm volatile("cp.async.ca.shared.global [%0], [%1], 16;" :: "r"(dst), "l"(src));
}

// ---------------- fused prep + weight conversion -----------------------------
__global__ void prep_kernel(const float* __restrict__ roi,
                            const float* __restrict__ img,
                            const int*  __restrict__ mask,
                            const float* __restrict__ eW,
                            const float* __restrict__ nW) {
    int idx = blockIdx.x * blockDim.x + threadIdx.x;
    int total = blockDim.x * gridDim.x;
    for (int i = idx; i < BI*HDIM; i += total) {
        float v = roi[i];
        g_ns[i] = v;
        g_ns16[i] = __float2bfloat16(v);
    }
    const int halfW = NLAYER*HDIM*HDIM/2;
    for (int i = idx; i < halfW; i += total) {
        float2 v = ((const float2*)eW)[i];
        ((__nv_bfloat162*)g_eW16)[i] = __floats2bfloat162_rn(v.x, v.y);
        float2 w = ((const float2*)nW)[i];
        ((__nv_bfloat162*)g_nW16)[i] = __floats2bfloat162_rn(w.x, w.y);
    }
    if (idx < BSZ*HDIM) {
        const float* p = img + (size_t)idx * 196;
        float s = 0.f;
        #pragma unroll 4
        for (int q = 0; q < 196; q++) s += p[q];
        g_e0[idx] = s * (1.0f/196.0f);
    }
    if (idx < BI) {
        const int* m = mask + idx * NROI;
        int s = 0;
        #pragma unroll
        for (int j = 0; j < NROI; j++) s += m[j];
        g_denom[idx] = (float)s + 1.0f;
    }
    if (idx < NPPAD) {
        if (idx < NPAIR) {
            int p = idx, ii = 0;
            while (p >= NROI - ii) { p -= NROI - ii; ii++; }
            g_pt[idx] = make_ushort2((unsigned short)ii, (unsigned short)(ii + p));
        } else {
            g_pt[idx] = make_ushort2(0, 0);
        }
    }
}

// ---------------- layer-0 edge matvec (float4 vectorized) -------------------
__global__ void em0_kernel(const float* __restrict__ W0,
                           const float* __restrict__ eb0) {
    int warp = (blockIdx.x * blockDim.x + threadIdx.x) >> 5;
    int lane = threadIdx.x & 31;
    if (warp >= BSZ*HDIM) return;
    int b = warp >> 9;
    int o = warp & 511;
    const float4* e4 = (const float4*)(g_e0 + b*HDIM);
    const float4* w4 = (const float4*)(W0 + (size_t)o*HDIM);
    float s = 0.f;
    #pragma unroll
    for (int it = 0; it < 4; it++) {
        float4 e = e4[lane + it*32];
        float4 w = w4[lane + it*32];
        s += e.x*w.x + e.y*w.y + e.z*w.z + e.w*w.w;
    }
    #pragma unroll
    for (int d = 16; d; d >>= 1) s += __shfl_xor_sync(0xffffffffu, s, d);
    if (lane == 0) g_em0[warp] = s + eb0[o];
}

// ---- layer-0 fused: full-layout edge write + agg + node update, 2 i/block --
__global__ void edge0_fused_kernel(const int* __restrict__ mask) {
    int bi0 = blockIdx.x * 2;            // even bi; same b as bi0+1
    int b = bi0 >> 6, iA = bi0 & 63, iB = iA + 1;
    int o = threadIdx.x * 2;
    const float* nmb = g_nm + (size_t)b * NROI * HDIM;
    __nv_bfloat16* ebA = g_ebuf[0] + ((size_t)b * NROI * NROI + (size_t)iA * NROI) * HDIM;
    __nv_bfloat16* ebB = ebA + (size_t)NROI * HDIM;
    const int* mrowA = mask + bi0 * NROI;
    const int* mrowB = mrowA + NROI;
    float2 nmiA = *(const float2*)(nmb + (size_t)iA*HDIM + o);
    float2 nmiB = *(const float2*)(nmb + (size_t)iB*HDIM + o);
    float2 em2 = *(const float2*)(g_em0 + b*HDIM + o);
    float baseA0 = nmiA.x + em2.x, baseA1 = nmiA.y + em2.y;
    float baseB0 = nmiB.x + em2.x, baseB1 = nmiB.y + em2.y;
    float aggA0 = 0.f, aggA1 = 0.f, aggB0 = 0.f, aggB1 = 0.f;
    #pragma unroll 8
    for (int j = 0; j < NROI; j++) {
        float2 nj = *(const float2*)(nmb + (size_t)j*HDIM + o);
        float eA0 = leaky(baseA0 + nj.x);
        float eA1 = leaky(baseA1 + nj.y);
        float eB0 = leaky(baseB0 + nj.x);
        float eB1 = leaky(baseB1 + nj.y);
        *(__nv_bfloat162*)(ebA + (size_t)j*HDIM + o) = __floats2bfloat162_rn(eA0, eA1);
        *(__nv_bfloat162*)(ebB + (size_t)j*HDIM + o) = __floats2bfloat162_rn(eB0, eB1);
        float mA = (float)mrowA[j];
        float mB = (float)mrowB[j];
        aggA0 += eA0 * nj.x * mA;
        aggA1 += eA1 * nj.y * mA;
        aggB0 += eB0 * nj.x * mB;
        aggB1 += eB1 * nj.y * mB;
    }
    float dnA = g_denom[bi0], dnB = g_denom[bi0 + 1];
    size_t baseAo = (size_t)bi0*HDIM + o;
    size_t baseBo = baseAo + HDIM;
    float nsA0 = g_ns[baseAo]     + leaky((nmiA.x + aggA0) / dnA);
    float nsA1 = g_ns[baseAo + 1] + leaky((nmiA.y + aggA1) / dnA);
    float nsB0 = g_ns[baseBo]     + leaky((nmiB.x + aggB0) / dnB);
    float nsB1 = g_ns[baseBo + 1] + leaky((nmiB.y + aggB1) / dnB);
    g_ns[baseAo] = nsA0;  g_ns[baseAo + 1] = nsA1;
    g_ns[baseBo] = nsB0;  g_ns[baseBo + 1] = nsB1;
    *(__nv_bfloat162*)(g_ns16 + baseAo) = __floats2bfloat162_rn(nsA0, nsA1);
    *(__nv_bfloat162*)(g_ns16 + baseBo) = __floats2bfloat162_rn(nsB0, nsB1);
}

// ---------------- agg + node update (layers 1..4), contiguous e rows ---------
__global__ void agg_node_kernel(int cur, const int* __restrict__ mask) {
    int bi0 = blockIdx.x * 2;
    int b = bi0 >> 6, iA = bi0 & 63, iB = iA + 1;
    int o = threadIdx.x * 2;
    const float* nmb = g_nm + (size_t)b * NROI * HDIM;
    const __nv_bfloat16* ebA = g_ebuf[cur] +
        ((size_t)b * NROI * NROI + (size_t)iA * NROI) * HDIM;
    const __nv_bfloat16* ebB = ebA + (size_t)NROI * HDIM;
    const int* mrowA = mask + bi0 * NROI;
    const int* mrowB = mrowA + NROI;
    float aggA0 = 0.f, aggA1 = 0.f, aggB0 = 0.f, aggB1 = 0.f;
    #pragma unroll 8
    for (int j = 0; j < NROI; j++) {
        float2 nj = *(const float2*)(nmb + (size_t)j*HDIM + o);
        __nv_bfloat162 eA2 = *(const __nv_bfloat162*)(ebA + (size_t)j*HDIM + o);
        __nv_bfloat162 eB2 = *(const __nv_bfloat162*)(ebB + (size_t)j*HDIM + o);
        float2 efA = __bfloat1622float2(eA2);
        float2 efB = __bfloat1622float2(eB2);
        float mA = (float)mrowA[j];
        float mB = (float)mrowB[j];
        aggA0 += efA.x * nj.x * mA;
        aggA1 += efA.y * nj.y * mA;
        aggB0 += efB.x * nj.x * mB;
        aggB1 += efB.y * nj.y * mB;
    }
    float2 nmiA = *(const float2*)(g_nm + (size_t)bi0*HDIM + o);
    float2 nmiB = *(const float2*)(g_nm + (size_t)(bi0+1)*HDIM + o);
    float dnA = g_denom[bi0], dnB = g_denom[bi0 + 1];
    size_t baseAo = (size_t)bi0*HDIM + o;
    size_t baseBo = baseAo + HDIM;
    float nsA0 = g_ns[baseAo]     + leaky((nmiA.x + aggA0) / dnA);
    float nsA1 = g_ns[baseAo + 1] + leaky((nmiA.y + aggA1) / dnA);
    float nsB0 = g_ns[baseBo]     + leaky((nmiB.x + aggB0) / dnB);
    float nsB1 = g_ns[baseBo + 1] + leaky((nmiB.y + aggB1) / dnB);
    g_ns[baseAo] = nsA0;  g_ns[baseAo + 1] = nsA1;
    g_ns[baseBo] = nsB0;  g_ns[baseBo + 1] = nsB1;
    *(__nv_bfloat162*)(g_ns16 + baseAo) = __floats2bfloat162_rn(nsA0, nsA1);
    *(__nv_bfloat162*)(g_ns16 + baseBo) = __floats2bfloat162_rn(nsB0, nsB1);
}

// ======================= shared GEMM params =================================
#define KC    32
#define NIT   (HDIM/KC)     // 16
#define STRD  40            // conflict-free smem stride (elems)

// ---------------- nm GEMM (bf16 MMA), 64x64 tiles, grid (8,8) ---------------
__global__ __launch_bounds__(256) void nm_mma_kernel(
    int t, const float* __restrict__ bt)
{
    __shared__ __nv_bfloat16 As[2][64*STRD];
    __shared__ __nv_bfloat16 Bs[2][64*STRD];

    int tid  = threadIdx.x;
    int wid  = tid >> 5, lane = tid & 31;
    int wm   = wid & 3, wn = wid >> 2;
    int r0   = blockIdx.y * 64;
    int o0   = blockIdx.x * 64;

    const __nv_bfloat16* A  = g_ns16 + (size_t)r0 * HDIM;
    const __nv_bfloat16* Bw = g_nW16 + (size_t)t * HDIM * HDIM + (size_t)o0 * HDIM;

    float acc[4][4] = {};

    int arow = tid >> 2, acol = (tid & 3) * 8;

    {
        cpa16(smem_u32(&As[0][arow*STRD + acol]), A + (size_t)arow*HDIM + acol);
        cpa16(smem_u32(&Bs[0][arow*STRD + acol]), Bw + (size_t)arow*HDIM + acol);
        asm volatile("cp.async.commit_group;");
    }

    for (int it = 0; it < NIT; it++) {
        asm volatile("cp.async.wait_group 0;");
        __syncthreads();
        if (it + 1 < NIT) {
            int st = (it + 1) & 1;
            int k0 = (it + 1) * KC;
            cpa16(smem_u32(&As[st][arow*STRD + acol]), A + (size_t)arow*HDIM + k0 + acol);
            cpa16(smem_u32(&Bs[st][arow*STRD + acol]), Bw + (size_t)arow*HDIM + k0 + acol);
            asm volatile("cp.async.commit_group;");
        }
        int st = it & 1;
        unsigned aBase = smem_u32(&As[st][(wm*16 + (lane & 15))*STRD + (lane >> 4)*8]);
        unsigned bBase = smem_u32(&Bs[st][(wn*32 + ((lane >> 4) << 3) + (lane & 7))*STRD
                                          + (((lane >> 3) & 1) << 3)]);
        #pragma unroll
        for (int ks = 0; ks < KC; ks += 16) {
            unsigned a0,a1,a2,a3;
            asm volatile("ldmatrix.sync.aligned.m8n8.x4.shared.b16 {%0,%1,%2,%3},[%4];"
                : "=r"(a0),"=r"(a1),"=r"(a2),"=r"(a3) : "r"(aBase + (unsigned)(ks*2)));
            #pragma unroll
            for (int p2 = 0; p2 < 2; p2++) {
                unsigned b0,b1,b2,b3;
                asm volatile("ldmatrix.sync.aligned.m8n8.x4.shared.b16 {%0,%1,%2,%3},[%4];"
                    : "=r"(b0),"=r"(b1),"=r"(b2),"=r"(b3)
                    : "r"(bBase + (unsigned)((p2*16*STRD + ks) * 2)));
                float* c0 = acc[p2*2];
                asm volatile("mma.sync.aligned.m16n8k16.row.col.f32.bf16.bf16.f32 "
                    "{%0,%1,%2,%3},{%4,%5,%6,%7},{%8,%9},{%0,%1,%2,%3};"
                    : "+f"(c0[0]),"+f"(c0[1]),"+f"(c0[2]),"+f"(c0[3])
                    : "r"(a0),"r"(a1),"r"(a2),"r"(a3),"r"(b0),"r"(b1));
                float* c1 = acc[p2*2+1];
                asm volatile("mma.sync.aligned.m16n8k16.row.col.f32.bf16.bf16.f32 "
                    "{%0,%1,%2,%3},{%4,%5,%6,%7},{%8,%9},{%0,%1,%2,%3};"
                    : "+f"(c1[0]),"+f"(c1[1]),"+f"(c1[2]),"+f"(c1[3])
                    : "r"(a0),"r"(a1),"r"(a2),"r"(a3),"r"(b2),"r"(b3));
            }
        }
        __syncthreads();
    }

    int r1 = r0 + wm*16 + (lane >> 2);
    int r2 = r1 + 8;
    #pragma unroll
    for (int p = 0; p < 4; p++) {
        int o = o0 + wn*32 + p*8 + (lane & 3)*2;
        float2 bo = *(const float2*)(bt + o);
        float2 v1; v1.x = acc[p][0] + bo.x; v1.y = acc[p][1] + bo.y;
        float2 v2; v2.x = acc[p][2] + bo.x; v2.y = acc[p][3] + bo.y;
        *(float2*)(g_nm + (size_t)r1*HDIM + o) = v1;
        *(float2*)(g_nm + (size_t)r2*HDIM + o) = v2;
    }
}

// ===== fused edge GEMM over symmetric pairs (layers 1..4), 2-stage ==========
// A rows fetched from full layout via g_pt indirection; epilogue writes both
// mirror locations. Half FLOPs retained.
__global__ __launch_bounds__(256) void gemm_pairs_kernel(
    int t, const float* __restrict__ ebt, int src, int dst)
{
    __shared__ __nv_bfloat16 As[2][64*STRD];
    __shared__ __nv_bfloat16 Bs[2][128*STRD];

    int tid  = threadIdx.x;
    int wid  = tid >> 5, lane = tid & 31;
    int wm   = wid & 3, wn = wid >> 2;
    int b    = blockIdx.z;
    int r0   = blockIdx.y * 64;
    int o0   = blockIdx.x * 128;

    const __nv_bfloat16* Efull = g_ebuf[src] + (size_t)b * NROI * NROI * HDIM;
    const __nv_bfloat16* Bw = g_eW16 + (size_t)t * HDIM * HDIM + (size_t)o0 * HDIM;

    float acc[8][4] = {};

    int arow = tid >> 2, acol = (tid & 3) * 8;
    int brow = tid >> 1, bcol = (tid & 1) * 16;

    // per-thread A row via pair table (full-layout row i*64+j)
    ushort2 apj = g_pt[r0 + arow];
    const __nv_bfloat16* Arow = Efull + ((size_t)apj.x * NROI + apj.y) * HDIM;

    {
        cpa16(smem_u32(&As[0][arow*STRD + acol]), Arow + acol);
        unsigned sB = smem_u32(&Bs[0][brow*STRD + bcol]);
        const __nv_bfloat16* gB = Bw + (size_t)brow*HDIM + bcol;
        cpa16(sB, gB); cpa16(sB+16, gB+8);
        asm volatile("cp.async.commit_group;");
    }

    for (int it = 0; it < NIT; it++) {
        asm volatile("cp.async.wait_group 0;");
        __syncthreads();
        if (it + 1 < NIT) {
            int st = (it + 1) & 1;
            int k0 = (it + 1) * KC;
            cpa16(smem_u32(&As[st][arow*STRD + acol]), Arow + k0 + acol);
            unsigned sB = smem_u32(&Bs[st][brow*STRD + bcol]);
            const __nv_bfloat16* gB = Bw + (size_t)brow*HDIM + k0 + bcol;
            cpa16(sB, gB); cpa16(sB+16, gB+8);
            asm volatile("cp.async.commit_group;");
        }
        int st = it & 1;
        unsigned aBase = smem_u32(&As[st][(wm*16 + (lane & 15))*STRD + (lane >> 4)*8]);
        unsigned bBase = smem_u32(&Bs[st][(wn*64 + ((lane >> 4) << 3) + (lane & 7))*STRD
                                          + (((lane >> 3) & 1) << 3)]);
        #pragma unroll
        for (int ks = 0; ks < KC; ks += 16) {
            unsigned a0,a1,a2,a3;
            asm volatile("ldmatrix.sync.aligned.m8n8.x4.shared.b16 {%0,%1,%2,%3},[%4];"
                : "=r"(a0),"=r"(a1),"=r"(a2),"=r"(a3) : "r"(aBase + (unsigned)(ks*2)));
            #pragma unroll
            for (int p2 = 0; p2 < 4; p2++) {
                unsigned b0,b1,b2,b3;
                asm volatile("ldmatrix.sync.aligned.m8n8.x4.shared.b16 {%0,%1,%2,%3},[%4];"
                    : "=r"(b0),"=r"(b1),"=r"(b2),"=r"(b3)
                    : "r"(bBase + (unsigned)((p2*16*STRD + ks) * 2)));
                float* c0 = acc[p2*2];
                asm volatile("mma.sync.aligned.m16n8k16.row.col.f32.bf16.bf16.f32 "
                    "{%0,%1,%2,%3},{%4,%5,%6,%7},{%8,%9},{%0,%1,%2,%3};"
                    : "+f"(c0[0]),"+f"(c0[1]),"+f"(c0[2]),"+f"(c0[3])
                    : "r"(a0),"r"(a1),"r"(a2),"r"(a3),"r"(b0),"r"(b1));
                float* c1 = acc[p2*2+1];
                asm volatile("mma.sync.aligned.m16n8k16.row.col.f32.bf16.bf16.f32 "
                    "{%0,%1,%2,%3},{%4,%5,%6,%7},{%8,%9},{%0,%1,%2,%3};"
                    : "+f"(c1[0]),"+f"(c1[1]),"+f"(c1[2]),"+f"(c1[3])
                    : "r"(a0),"r"(a1),"r"(a2),"r"(a3),"r"(b2),"r"(b3));
            }
        }
        __syncthreads();
    }

    // ---- epilogue: leaky + mirrored full-layout bf16 write ----
    int rbase = wm*16 + (lane >> 2);
    int r1 = rbase, r2 = rbase + 8;
    ushort2 pj1 = g_pt[r0 + r1];
    ushort2 pj2 = g_pt[r0 + r2];
    const float* nmb = g_nm + (size_t)b * NROI * HDIM;
    __nv_bfloat16* Edst = g_ebuf[dst] + (size_t)b * NROI * NROI * HDIM;
    __nv_bfloat16* d1a = Edst + ((size_t)pj1.x * NROI + pj1.y) * HDIM;
    __nv_bfloat16* d1b = Edst + ((size_t)pj1.y * NROI + pj1.x) * HDIM;
    __nv_bfloat16* d2a = Edst + ((size_t)pj2.x * NROI + pj2.y) * HDIM;
    __nv_bfloat16* d2b = Edst + ((size_t)pj2.y * NROI + pj2.x) * HDIM;

    #pragma unroll
    for (int p = 0; p < 8; p++) {
        int o = o0 + wn*64 + p*8 + (lane & 3)*2;
        float2 ebv = *(const float2*)(ebt + o);
        float2 i1 = *(const float2*)(nmb + (size_t)pj1.x*HDIM + o);
        float2 j1 = *(const float2*)(nmb + (size_t)pj1.y*HDIM + o);
        float2 i2 = *(const float2*)(nmb + (size_t)pj2.x*HDIM + o);
        float2 j2 = *(const float2*)(nmb + (size_t)pj2.y*HDIM + o);
        float e00 = leaky(acc[p][0] + i1.x + j1.x + ebv.x);
        float e01 = leaky(acc[p][1] + i1.y + j1.y + ebv.y);
        float e10 = leaky(acc[p][2] + i2.x + j2.x + ebv.x);
        float e11 = leaky(acc[p][3] + i2.y + j2.y + ebv.y);
        __nv_bfloat162 v1 = __floats2bfloat162_rn(e00, e01);
        __nv_bfloat162 v2 = __floats2bfloat162_rn(e10, e11);
        *(__nv_bfloat162*)(d1a + o) = v1;
        *(__nv_bfloat162*)(d1b + o) = v1;
        *(__nv_bfloat162*)(d2a + o) = v2;
        *(__nv_bfloat162*)(d2b + o) = v2;
    }
}

// ---------------- output: concat broadcast of node_state --------------------
__global__ void out_kernel(float* __restrict__ out) {
    size_t f = (size_t)blockIdx.x * blockDim.x + threadIdx.x;
    size_t total4 = (size_t)BSZ*NROI*NROI*1024 / 4;
    if (f >= total4) return;
    size_t flat = f * 4;
    int c = (int)(flat & 1023);
    size_t bij = flat >> 10;
    int j = (int)(bij & 63);
    size_t bi = bij >> 6;            // b*64+i
    size_t b  = bi >> 6;
    const float* src = (c < 512)
        ? (g_ns + bi * HDIM + c)
        : (g_ns + (b*64 + j) * HDIM + (c - 512));
    *(float4*)(out + flat) = *(const float4*)src;
}

// ---------------- host launch ------------------------------------------------
extern "C" void kernel_launch(void* const* d_in, const int* in_sizes, int n_in,
                              void* d_out, int out_size) {
    const float* roi = (const float*)d_in[0];
    const float* img = (const float*)d_in[1];
    const float* nW  = (const float*)d_in[2];
    const float* nb  = (const float*)d_in[3];
    const float* eW  = (const float*)d_in[4];
    const float* eb  = (const float*)d_in[5];
    const int*   msk = (const int*)d_in[6];
    float* out = (float*)d_out;

    prep_kernel<<<2048, 256>>>(roi, img, msk, eW, nW);

    for (int t = 0; t < NLAYER; t++) {
        nm_mma_kernel<<<dim3(8, 8), 256>>>(t, nb + (size_t)t*HDIM);
        if (t == 0) {
            em0_kernel<<<512, 256>>>(eW, eb);
            edge0_fused_kernel<<<256, 256>>>(msk);
        } else {
            int dst = t & 1;
            int src = dst ^ 1;
            gemm_pairs_kernel<<<dim3(4, 33, 8), 256>>>(
                t, eb + (size_t)t*HDIM, src, dst);
            agg_node_kernel<<<256, 256>>>(dst, msk);
        }
    }

    out_kernel<<<32768, 256>>>(out);
}

// round 16
// speedup vs baseline: 1.0792x; 1.0792x over previous
#include <cuda_runtime.h>
#include <cuda_bf16.h>
#include <cstdint>

#define BSZ   8
#define NROI  64
#define HDIM  512
#define NLAYER 5
#define BI    (BSZ*NROI)                     // 512 (b,i) pairs
#define NPAIR 2080                           // i<=j pairs
#define NPPAD 2112                           // 33*64 padded

// ---------------- scratch (device globals; no allocation allowed) ----------
__device__ __nv_bfloat16 g_ebuf[2][(size_t)BSZ*NPPAD*HDIM]; // symmetric edge_state, pair-compact
__device__ __nv_bfloat16 g_eW16[(size_t)NLAYER*HDIM*HDIM];  // bf16 edge weights
__device__ __nv_bfloat16 g_nW16[(size_t)NLAYER*HDIM*HDIM];  // bf16 node weights
__device__ __nv_bfloat16 g_ns16[BI*HDIM];               // bf16 mirror of node_state
__device__ float g_nm[BI*HDIM];
__device__ float g_ns[BI*HDIM];
__device__ float g_denom[BI];
__device__ float g_em0[BSZ*HDIM];                       // layer-0 edge matvec (incl. bias)
__device__ float g_e0[BSZ*HDIM];                        // mean of img_featmap
__device__ ushort2 g_pt[NPPAD];                         // pair p -> (i,j), i<=j

__device__ __forceinline__ float leaky(float x) { return x >= 0.f ? x : 0.01f * x; }
__device__ __forceinline__ unsigned smem_u32(const void* p) {
    return (unsigned)__cvta_generic_to_shared(p);
}
__device__ __forceinline__ void cpa16(unsigned dst, const void* src) {
    asm volatile("cp.async.ca.shared.global [%0], [%1], 16;" :: "r"(dst), "l"(src));
}

// ---------------- fused prep + weight conversion -----------------------------
__global__ void prep_kernel(const float* __restrict__ roi,
                            const float* __restrict__ img,
                            const int*  __restrict__ mask,
                            const float* __restrict__ eW,
                            const float* __restrict__ nW) {
    int idx = blockIdx.x * blockDim.x + threadIdx.x;
    int total = blockDim.x * gridDim.x;
    for (int i = idx; i < BI*HDIM; i += total) {
        float v = roi[i];
        g_ns[i] = v;
        g_ns16[i] = __float2bfloat16(v);
    }
    const int halfW = NLAYER*HDIM*HDIM/2;
    for (int i = idx; i < halfW; i += total) {
        float2 v = ((const float2*)eW)[i];
        ((__nv_bfloat162*)g_eW16)[i] = __floats2bfloat162_rn(v.x, v.y);
        float2 w = ((const float2*)nW)[i];
        ((__nv_bfloat162*)g_nW16)[i] = __floats2bfloat162_rn(w.x, w.y);
    }
    if (idx < BSZ*HDIM) {
        const float* p = img + (size_t)idx * 196;
        float s = 0.f;
        #pragma unroll 4
        for (int q = 0; q < 196; q++) s += p[q];
        g_e0[idx] = s * (1.0f/196.0f);
    }
    if (idx < BI) {
        const int* m = mask + idx * NROI;
        int s = 0;
        #pragma unroll
        for (int j = 0; j < NROI; j++) s += m[j];
        g_denom[idx] = (float)s + 1.0f;
    }
    if (idx < NPPAD) {
        if (idx < NPAIR) {
            int p = idx, ii = 0;
            while (p >= NROI - ii) { p -= NROI - ii; ii++; }
            g_pt[idx] = make_ushort2((unsigned short)ii, (unsigned short)(ii + p));
        } else {
            g_pt[idx] = make_ushort2(0, 0);
        }
    }
}

// ---------------- layer-0 edge matvec (float4 vectorized) -------------------
__global__ void em0_kernel(const float* __restrict__ W0,
                           const float* __restrict__ eb0) {
    int warp = (blockIdx.x * blockDim.x + threadIdx.x) >> 5;
    int lane = threadIdx.x & 31;
    if (warp >= BSZ*HDIM) return;
    int b = warp >> 9;
    int o = warp & 511;
    const float4* e4 = (const float4*)(g_e0 + b*HDIM);
    const float4* w4 = (const float4*)(W0 + (size_t)o*HDIM);
    float s = 0.f;
    #pragma unroll
    for (int it = 0; it < 4; it++) {
        float4 e = e4[lane + it*32];
        float4 w = w4[lane + it*32];
        s += e.x*w.x + e.y*w.y + e.z*w.z + e.w*w.w;
    }
    #pragma unroll
    for (int d = 16; d; d >>= 1) s += __shfl_xor_sync(0xffffffffu, s, d);
    if (lane == 0) g_em0[warp] = s + eb0[o];
}

// ---- layer-0 fused: edge write (pairs) + agg + node update ------------------
// Grid (2 o-halves, 512 bi), 256 threads; one (i, o) per thread for max
// occupancy (latency-bound kernel).
__global__ void edge0_fused_kernel(const int* __restrict__ mask) {
    int bi = blockIdx.y;
    int b = bi >> 6, i = bi & 63;
    int o = blockIdx.x * 256 + threadIdx.x;
    const float* nmb = g_nm + (size_t)b * NROI * HDIM;
    __nv_bfloat16* ebuf = g_ebuf[0] + (size_t)b * NPPAD * HDIM;
    const int* mrow = mask + bi * NROI;
    float nmi = nmb[(size_t)i*HDIM + o];
    float base = nmi + g_em0[b*HDIM + o];
    float agg = 0.f;
    int p = i;
    #pragma unroll 8
    for (int j = 0; j < NROI; j++) {
        float nj = nmb[(size_t)j*HDIM + o];
        float e = leaky(base + nj);
        if (j >= i)
            ebuf[(size_t)p*HDIM + o] = __float2bfloat16(e);
        float m = (float)mrow[j];
        agg += e * nj * m;
        p += (j < i) ? (63 - j) : 1;
    }
    float dn = g_denom[bi];
    size_t idx = (size_t)bi*HDIM + o;
    float ns = g_ns[idx] + leaky((nmi + agg) / dn);
    g_ns[idx] = ns;
    g_ns16[idx] = __float2bfloat16(ns);
}

// ---------------- agg + node update (layers 1..4) ----------------------------
// Grid (2 o-halves, 512 bi), 256 threads; one (i, o) per thread.
__global__ void agg_node_kernel(int cur, const int* __restrict__ mask) {
    int bi = blockIdx.y;
    int b = bi >> 6, i = bi & 63;
    int o = blockIdx.x * 256 + threadIdx.x;
    const float* nmb = g_nm + (size_t)b * NROI * HDIM;
    const __nv_bfloat16* ebuf = g_ebuf[cur] + (size_t)b * NPPAD * HDIM;
    const int* mrow = mask + bi * NROI;
    float agg = 0.f;
    int p = i;
    #pragma unroll 8
    for (int j = 0; j < NROI; j++) {
        float e = __bfloat162float(ebuf[(size_t)p*HDIM + o]);
        float m = (float)mrow[j];
        float nj = nmb[(size_t)j*HDIM + o];
        agg += e * nj * m;
        p += (j < i) ? (63 - j) : 1;
    }
    float nmi = g_nm[(size_t)bi*HDIM + o];
    float dn = g_denom[bi];
    size_t idx = (size_t)bi*HDIM + o;
    float ns = g_ns[idx] + leaky((nmi + agg) / dn);
    g_ns[idx] = ns;
    g_ns16[idx] = __float2bfloat16(ns);
}

// ======================= shared GEMM params =================================
#define KC    32
#define NIT   (HDIM/KC)     // 16
#define STRD  40            // conflict-free smem stride (elems)

// ---------------- nm GEMM (bf16 MMA), 64x64 tiles, grid (8,8) ---------------
__global__ __launch_bounds__(256) void nm_mma_kernel(
    int t, const float* __restrict__ bt)
{
    __shared__ __nv_bfloat16 As[2][64*STRD];
    __shared__ __nv_bfloat16 Bs[2][64*STRD];

    int tid  = threadIdx.x;
    int wid  = tid >> 5, lane = tid & 31;
    int wm   = wid & 3, wn = wid >> 2;
    int r0   = blockIdx.y * 64;
    int o0   = blockIdx.x * 64;

    const __nv_bfloat16* A  = g_ns16 + (size_t)r0 * HDIM;
    const __nv_bfloat16* Bw = g_nW16 + (size_t)t * HDIM * HDIM + (size_t)o0 * HDIM;

    float acc[4][4] = {};

    int arow = tid >> 2, acol = (tid & 3) * 8;

    {
        cpa16(smem_u32(&As[0][arow*STRD + acol]), A + (size_t)arow*HDIM + acol);
        cpa16(smem_u32(&Bs[0][arow*STRD + acol]), Bw + (size_t)arow*HDIM + acol);
        asm volatile("cp.async.commit_group;");
    }

    for (int it = 0; it < NIT; it++) {
        asm volatile("cp.async.wait_group 0;");
        __syncthreads();
        if (it + 1 < NIT) {
            int st = (it + 1) & 1;
            int k0 = (it + 1) * KC;
            cpa16(smem_u32(&As[st][arow*STRD + acol]), A + (size_t)arow*HDIM + k0 + acol);
            cpa16(smem_u32(&Bs[st][arow*STRD + acol]), Bw + (size_t)arow*HDIM + k0 + acol);
            asm volatile("cp.async.commit_group;");
        }
        int st = it & 1;
        unsigned aBase = smem_u32(&As[st][(wm*16 + (lane & 15))*STRD + (lane >> 4)*8]);
        unsigned bBase = smem_u32(&Bs[st][(wn*32 + ((lane >> 4) << 3) + (lane & 7))*STRD
                                          + (((lane >> 3) & 1) << 3)]);
        #pragma unroll
        for (int ks = 0; ks < KC; ks += 16) {
            unsigned a0,a1,a2,a3;
            asm volatile("ldmatrix.sync.aligned.m8n8.x4.shared.b16 {%0,%1,%2,%3},[%4];"
                : "=r"(a0),"=r"(a1),"=r"(a2),"=r"(a3) : "r"(aBase + (unsigned)(ks*2)));
            #pragma unroll
            for (int p2 = 0; p2 < 2; p2++) {
                unsigned b0,b1,b2,b3;
                asm volatile("ldmatrix.sync.aligned.m8n8.x4.shared.b16 {%0,%1,%2,%3},[%4];"
                    : "=r"(b0),"=r"(b1),"=r"(b2),"=r"(b3)
                    : "r"(bBase + (unsigned)((p2*16*STRD + ks) * 2)));
                float* c0 = acc[p2*2];
                asm volatile("mma.sync.aligned.m16n8k16.row.col.f32.bf16.bf16.f32 "
                    "{%0,%1,%2,%3},{%4,%5,%6,%7},{%8,%9},{%0,%1,%2,%3};"
                    : "+f"(c0[0]),"+f"(c0[1]),"+f"(c0[2]),"+f"(c0[3])
                    : "r"(a0),"r"(a1),"r"(a2),"r"(a3),"r"(b0),"r"(b1));
                float* c1 = acc[p2*2+1];
                asm volatile("mma.sync.aligned.m16n8k16.row.col.f32.bf16.bf16.f32 "
                    "{%0,%1,%2,%3},{%4,%5,%6,%7},{%8,%9},{%0,%1,%2,%3};"
                    : "+f"(c1[0]),"+f"(c1[1]),"+f"(c1[2]),"+f"(c1[3])
                    : "r"(a0),"r"(a1),"r"(a2),"r"(a3),"r"(b2),"r"(b3));
            }
        }
        __syncthreads();
    }

    int r1 = r0 + wm*16 + (lane >> 2);
    int r2 = r1 + 8;
    #pragma unroll
    for (int p = 0; p < 4; p++) {
        int o = o0 + wn*32 + p*8 + (lane & 3)*2;
        float2 bo = *(const float2*)(bt + o);
        float2 v1; v1.x = acc[p][0] + bo.x; v1.y = acc[p][1] + bo.y;
        float2 v2; v2.x = acc[p][2] + bo.x; v2.y = acc[p][3] + bo.y;
        *(float2*)(g_nm + (size_t)r1*HDIM + o) = v1;
        *(float2*)(g_nm + (size_t)r2*HDIM + o) = v2;
    }
}

// ===== fused edge GEMM over symmetric pairs (layers 1..4), 2-stage ==========
__global__ __launch_bounds__(256) void gemm_pairs_kernel(
    int t, const float* __restrict__ ebt, int src, int dst)
{
    __shared__ __nv_bfloat16 As[2][64*STRD];
    __shared__ __nv_bfloat16 Bs[2][128*STRD];

    int tid  = threadIdx.x;
    int wid  = tid >> 5, lane = tid & 31;
    int wm   = wid & 3, wn = wid >> 2;
    int b    = blockIdx.z;
    int r0   = blockIdx.y * 64;
    int o0   = blockIdx.x * 128;

    const __nv_bfloat16* A  = g_ebuf[src] + ((size_t)b * NPPAD + r0) * HDIM;
    const __nv_bfloat16* Bw = g_eW16 + (size_t)t * HDIM * HDIM + (size_t)o0 * HDIM;

    float acc[8][4] = {};

    int arow = tid >> 2, acol = (tid & 3) * 8;
    int brow = tid >> 1, bcol = (tid & 1) * 16;

    {
        cpa16(smem_u32(&As[0][arow*STRD + acol]), A + (size_t)arow*HDIM + acol);
        unsigned sB = smem_u32(&Bs[0][brow*STRD + bcol]);
        const __nv_bfloat16* gB = Bw + (size_t)brow*HDIM + bcol;
        cpa16(sB, gB); cpa16(sB+16, gB+8);
        asm volatile("cp.async.commit_group;");
    }

    for (int it = 0; it < NIT; it++) {
        asm volatile("cp.async.wait_group 0;");
        __syncthreads();
        if (it + 1 < NIT) {
            int st = (it + 1) & 1;
            int k0 = (it + 1) * KC;
            cpa16(smem_u32(&As[st][arow*STRD + acol]), A + (size_t)arow*HDIM + k0 + acol);
            unsigned sB = smem_u32(&Bs[st][brow*STRD + bcol]);
            const __nv_bfloat16* gB = Bw + (size_t)brow*HDIM + k0 + bcol;
            cpa16(sB, gB); cpa16(sB+16, gB+8);
            asm volatile("cp.async.commit_group;");
        }
        int st = it & 1;
        unsigned aBase = smem_u32(&As[st][(wm*16 + (lane & 15))*STRD + (lane >> 4)*8]);
        unsigned bBase = smem_u32(&Bs[st][(wn*64 + ((lane >> 4) << 3) + (lane & 7))*STRD
                                          + (((lane >> 3) & 1) << 3)]);
        #pragma unroll
        for (int ks = 0; ks < KC; ks += 16) {
            unsigned a0,a1,a2,a3;
            asm volatile("ldmatrix.sync.aligned.m8n8.x4.shared.b16 {%0,%1,%2,%3},[%4];"
                : "=r"(a0),"=r"(a1),"=r"(a2),"=r"(a3) : "r"(aBase + (unsigned)(ks*2)));
            #pragma unroll
            for (int p2 = 0; p2 < 4; p2++) {
                unsigned b0,b1,b2,b3;
                asm volatile("ldmatrix.sync.aligned.m8n8.x4.shared.b16 {%0,%1,%2,%3},[%4];"
                    : "=r"(b0),"=r"(b1),"=r"(b2),"=r"(b3)
                    : "r"(bBase + (unsigned)((p2*16*STRD + ks) * 2)));
                float* c0 = acc[p2*2];
                asm volatile("mma.sync.aligned.m16n8k16.row.col.f32.bf16.bf16.f32 "
                    "{%0,%1,%2,%3},{%4,%5,%6,%7},{%8,%9},{%0,%1,%2,%3};"
                    : "+f"(c0[0]),"+f"(c0[1]),"+f"(c0[2]),"+f"(c0[3])
                    : "r"(a0),"r"(a1),"r"(a2),"r"(a3),"r"(b0),"r"(b1));
                float* c1 = acc[p2*2+1];
                asm volatile("mma.sync.aligned.m16n8k16.row.col.f32.bf16.bf16.f32 "
                    "{%0,%1,%2,%3},{%4,%5,%6,%7},{%8,%9},{%0,%1,%2,%3};"
                    : "+f"(c1[0]),"+f"(c1[1]),"+f"(c1[2]),"+f"(c1[3])
                    : "r"(a0),"r"(a1),"r"(a2),"r"(a3),"r"(b2),"r"(b3));
            }
        }
        __syncthreads();
    }

    // ---- epilogue: leaky + pair-compact bf16 write ----
    int rbase = wm*16 + (lane >> 2);
    int r1 = rbase, r2 = rbase + 8;
    ushort2 pj1 = g_pt[r0 + r1];
    ushort2 pj2 = g_pt[r0 + r2];
    const float* nmb = g_nm + (size_t)b * NROI * HDIM;
    __nv_bfloat16* d1 = g_ebuf[dst] + ((size_t)b * NPPAD + r0 + r1) * HDIM;
    __nv_bfloat16* d2 = g_ebuf[dst] + ((size_t)b * NPPAD + r0 + r2) * HDIM;

    #pragma unroll
    for (int p = 0; p < 8; p++) {
        int o = o0 + wn*64 + p*8 + (lane & 3)*2;
        float2 ebv = *(const float2*)(ebt + o);
        float2 i1 = *(const float2*)(nmb + (size_t)pj1.x*HDIM + o);
        float2 j1 = *(const float2*)(nmb + (size_t)pj1.y*HDIM + o);
        float2 i2 = *(const float2*)(nmb + (size_t)pj2.x*HDIM + o);
        float2 j2 = *(const float2*)(nmb + (size_t)pj2.y*HDIM + o);
        float e00 = leaky(acc[p][0] + i1.x + j1.x + ebv.x);
        float e01 = leaky(acc[p][1] + i1.y + j1.y + ebv.y);
        float e10 = leaky(acc[p][2] + i2.x + j2.x + ebv.x);
        float e11 = leaky(acc[p][3] + i2.y + j2.y + ebv.y);
        *(__nv_bfloat162*)(d1 + o) = __floats2bfloat162_rn(e00, e01);
        *(__nv_bfloat162*)(d2 + o) = __floats2bfloat162_rn(e10, e11);
    }
}

// ---------------- output: concat broadcast of node_state --------------------
__global__ void out_kernel(float* __restrict__ out) {
    size_t f = (size_t)blockIdx.x * blockDim.x + threadIdx.x;
    size_t total4 = (size_t)BSZ*NROI*NROI*1024 / 4;
    if (f >= total4) return;
    size_t flat = f * 4;
    int c = (int)(flat & 1023);
    size_t bij = flat >> 10;
    int j = (int)(bij & 63);
    size_t bi = bij >> 6;            // b*64+i
    size_t b  = bi >> 6;
    const float* src = (c < 512)
        ? (g_ns + bi * HDIM + c)
        : (g_ns + (b*64 + j) * HDIM + (c - 512));
    __stcs((float4*)(out + flat), *(const float4*)src);
}

// ---------------- host launch ------------------------------------------------
extern "C" void kernel_launch(void* const* d_in, const int* in_sizes, int n_in,
                              void* d_out, int out_size) {
    const float* roi = (const float*)d_in[0];
    const float* img = (const float*)d_in[1];
    const float* nW  = (const float*)d_in[2];
    const float* nb  = (const float*)d_in[3];
    const float* eW  = (const float*)d_in[4];
    const float* eb  = (const float*)d_in[5];
    const int*   msk = (const int*)d_in[6];
    float* out = (float*)d_out;

    prep_kernel<<<2048, 256>>>(roi, img, msk, eW, nW);

    for (int t = 0; t < NLAYER; t++) {
        nm_mma_kernel<<<dim3(8, 8), 256>>>(t, nb + (size_t)t*HDIM);
        if (t == 0) {
            em0_kernel<<<512, 256>>>(eW, eb);
            edge0_fused_kernel<<<dim3(2, 512), 256>>>(msk);
        } else {
            int dst = t & 1;
            int src = dst ^ 1;
            gemm_pairs_kernel<<<dim3(4, 33, 8), 256>>>(
                t, eb + (size_t)t*HDIM, src, dst);
            agg_node_kernel<<<dim3(2, 512), 256>>>(dst, msk);
        }
    }

    out_kernel<<<32768, 256>>>(out);
}

// round 17
// speedup vs baseline: 1.1099x; 1.0284x over previous
#include <cuda_runtime.h>
#include <cuda_bf16.h>
#include <cstdint>

#define BSZ   8
#define NROI  64
#define HDIM  512
#define NLAYER 5
#define BI    (BSZ*NROI)                     // 512 (b,i) pairs
#define NPAIR 2080                           // i<=j pairs
#define NPPAD 2112                           // 33*64 padded

// ---------------- scratch (device globals; no allocation allowed) ----------
__device__ __nv_bfloat16 g_ebuf[2][(size_t)BSZ*NPPAD*HDIM]; // symmetric edge_state, pair-compact
__device__ __nv_bfloat16 g_eW16[(size_t)NLAYER*HDIM*HDIM];  // bf16 edge weights
__device__ __nv_bfloat16 g_nW16[(size_t)NLAYER*HDIM*HDIM];  // bf16 node weights
__device__ __nv_bfloat16 g_ns16[BI*HDIM];               // bf16 mirror of node_state
__device__ float g_nm[BI*HDIM];
__device__ float g_ns[BI*HDIM];
__device__ float g_denom[BI];
__device__ float g_em0[BSZ*HDIM];                       // layer-0 edge matvec (incl. bias)
__device__ float g_e0[BSZ*HDIM];                        // mean of img_featmap
__device__ ushort2 g_pt[NPPAD];                         // pair p -> (i,j), i<=j

__device__ __forceinline__ float leaky(float x) { return x >= 0.f ? x : 0.01f * x; }
__device__ __forceinline__ unsigned smem_u32(const void* p) {
    return (unsigned)__cvta_generic_to_shared(p);
}
__device__ __forceinline__ void cpa16(unsigned dst, const void* src) {
    asm volatile("cp.async.ca.shared.global [%0], [%1], 16;" :: "r"(dst), "l"(src));
}

// ---------------- fused prep + weight conversion -----------------------------
__global__ void prep_kernel(const float* __restrict__ roi,
                            const float* __restrict__ img,
                            const int*  __restrict__ mask,
                            const float* __restrict__ eW,
                            const float* __restrict__ nW) {
    int idx = blockIdx.x * blockDim.x + threadIdx.x;
    int total = blockDim.x * gridDim.x;
    for (int i = idx; i < BI*HDIM; i += total) {
        float v = roi[i];
        g_ns[i] = v;
        g_ns16[i] = __float2bfloat16(v);
    }
    const int halfW = NLAYER*HDIM*HDIM/2;
    for (int i = idx; i < halfW; i += total) {
        float2 v = ((const float2*)eW)[i];
        ((__nv_bfloat162*)g_eW16)[i] = __floats2bfloat162_rn(v.x, v.y);
        float2 w = ((const float2*)nW)[i];
        ((__nv_bfloat162*)g_nW16)[i] = __floats2bfloat162_rn(w.x, w.y);
    }
    if (idx < BSZ*HDIM) {
        const float* p = img + (size_t)idx * 196;
        float s = 0.f;
        #pragma unroll 4
        for (int q = 0; q < 196; q++) s += p[q];
        g_e0[idx] = s * (1.0f/196.0f);
    }
    if (idx < BI) {
        const int* m = mask + idx * NROI;
        int s = 0;
        #pragma unroll
        for (int j = 0; j < NROI; j++) s += m[j];
        g_denom[idx] = (float)s + 1.0f;
    }
    if (idx < NPPAD) {
        if (idx < NPAIR) {
            int p = idx, ii = 0;
            while (p >= NROI - ii) { p -= NROI - ii; ii++; }
            g_pt[idx] = make_ushort2((unsigned short)ii, (unsigned short)(ii + p));
        } else {
            g_pt[idx] = make_ushort2(0, 0);
        }
    }
}

// ---------------- layer-0 edge matvec (float4 vectorized) -------------------
__global__ void em0_kernel(const float* __restrict__ W0,
                           const float* __restrict__ eb0) {
    int warp = (blockIdx.x * blockDim.x + threadIdx.x) >> 5;
    int lane = threadIdx.x & 31;
    if (warp >= BSZ*HDIM) return;
    int b = warp >> 9;
    int o = warp & 511;
    const float4* e4 = (const float4*)(g_e0 + b*HDIM);
    const float4* w4 = (const float4*)(W0 + (size_t)o*HDIM);
    float s = 0.f;
    #pragma unroll
    for (int it = 0; it < 4; it++) {
        float4 e = e4[lane + it*32];
        float4 w = w4[lane + it*32];
        s += e.x*w.x + e.y*w.y + e.z*w.z + e.w*w.w;
    }
    #pragma unroll
    for (int d = 16; d; d >>= 1) s += __shfl_xor_sync(0xffffffffu, s, d);
    if (lane == 0) g_em0[warp] = s + eb0[o];
}

// ---- layer-0 fused: edge write (pairs) + agg + node update ------------------
// Grid (2 o-halves, 512 bi), 256 threads; one (i, o) per thread. Split j-loop
// with incremental pointer stepping (pure IADD address chain).
__global__ void edge0_fused_kernel(const int* __restrict__ mask) {
    int bi = blockIdx.y;
    int b = bi >> 6, i = bi & 63;
    int o = blockIdx.x * 256 + threadIdx.x;
    const float* nmp = g_nm + (size_t)b * NROI * HDIM + o;     // row j walker
    __nv_bfloat16* ebuf = g_ebuf[0] + (size_t)b * NPPAD * HDIM + o;
    const int* mrow = mask + bi * NROI;
    float nmi = nmp[(size_t)i * HDIM];
    float base = nmi + g_em0[b*HDIM + o];
    float agg = 0.f;

    // segment 1: j in [0, i)  (no edge write; e row offset steps (63-j)*HDIM)
    long eoff = (long)i * HDIM;
    long d = (long)63 * HDIM;
    const float* nmj = nmp;
    for (int j = 0; j < i; j++) {
        float nj = *nmj;
        float e = leaky(base + nj);
        agg += e * nj * (float)mrow[j];
        nmj += HDIM;
        eoff += d; d -= HDIM;
    }
    // segment 2: j in [i, 64)  (edge write; e row offset steps HDIM)
    __nv_bfloat16* ew = ebuf + eoff;
    for (int j = i; j < NROI; j++) {
        float nj = *nmj;
        float e = leaky(base + nj);
        *ew = __float2bfloat16(e);
        agg += e * nj * (float)mrow[j];
        nmj += HDIM;
        ew += HDIM;
    }

    float dn = g_denom[bi];
    size_t idx = (size_t)bi*HDIM + o;
    float ns = g_ns[idx] + leaky((nmi + agg) / dn);
    g_ns[idx] = ns;
    g_ns16[idx] = __float2bfloat16(ns);
}

// ---------------- agg + node update (layers 1..4) ----------------------------
// Grid (2 o-halves, 512 bi), 256 threads; one (i, o) per thread; split loop.
__global__ void agg_node_kernel(int cur, const int* __restrict__ mask) {
    int bi = blockIdx.y;
    int b = bi >> 6, i = bi & 63;
    int o = blockIdx.x * 256 + threadIdx.x;
    const float* nmj = g_nm + (size_t)b * NROI * HDIM + o;
    const __nv_bfloat16* ebuf = g_ebuf[cur] + (size_t)b * NPPAD * HDIM + o;
    const int* mrow = mask + bi * NROI;
    float agg = 0.f;

    // segment 1: j < i, e offset steps (63-j)*HDIM
    const __nv_bfloat16* ep = ebuf + (size_t)i * HDIM;
    long d = (long)63 * HDIM;
    for (int j = 0; j < i; j++) {
        float e = __bfloat162float(*ep);
        float nj = *nmj;
        agg += e * nj * (float)mrow[j];
        nmj += HDIM;
        ep += d; d -= HDIM;
    }
    // segment 2: j >= i, e offset steps HDIM
    for (int j = i; j < NROI; j++) {
        float e = __bfloat162float(*ep);
        float nj = *nmj;
        agg += e * nj * (float)mrow[j];
        nmj += HDIM;
        ep += HDIM;
    }

    float nmi = g_nm[(size_t)bi*HDIM + o];
    float dn = g_denom[bi];
    size_t idx = (size_t)bi*HDIM + o;
    float ns = g_ns[idx] + leaky((nmi + agg) / dn);
    g_ns[idx] = ns;
    g_ns16[idx] = __float2bfloat16(ns);
}

// ======================= shared GEMM params =================================
#define KC    32
#define NIT   (HDIM/KC)     // 16
#define STRD  40            // conflict-free smem stride (elems)

// ---------------- nm GEMM (bf16 MMA), 32x64 tiles, grid (8,16), 128 thr -----
__global__ __launch_bounds__(128) void nm_mma_kernel(
    int t, const float* __restrict__ bt)
{
    __shared__ __nv_bfloat16 As[2][32*STRD];
    __shared__ __nv_bfloat16 Bs[2][64*STRD];

    int tid  = threadIdx.x;
    int wid  = tid >> 5, lane = tid & 31;
    int wm   = wid & 1, wn = wid >> 1;
    int r0   = blockIdx.y * 32;
    int o0   = blockIdx.x * 64;

    const __nv_bfloat16* A  = g_ns16 + (size_t)r0 * HDIM;
    const __nv_bfloat16* Bw = g_nW16 + (size_t)t * HDIM * HDIM + (size_t)o0 * HDIM;

    float acc[4][4] = {};

    int arow = tid >> 2, acol = (tid & 3) * 8;    // 32 rows x 32 k
    int brow = tid >> 1, bcol = (tid & 1) * 16;   // 64 rows x 32 k (2x16B)

    {
        cpa16(smem_u32(&As[0][arow*STRD + acol]), A + (size_t)arow*HDIM + acol);
        unsigned sB = smem_u32(&Bs[0][brow*STRD + bcol]);
        const __nv_bfloat16* gB = Bw + (size_t)brow*HDIM + bcol;
        cpa16(sB, gB); cpa16(sB+16, gB+8);
        asm volatile("cp.async.commit_group;");
    }

    for (int it = 0; it < NIT; it++) {
        asm volatile("cp.async.wait_group 0;");
        __syncthreads();
        if (it + 1 < NIT) {
            int st = (it + 1) & 1;
            int k0 = (it + 1) * KC;
            cpa16(smem_u32(&As[st][arow*STRD + acol]), A + (size_t)arow*HDIM + k0 + acol);
            unsigned sB = smem_u32(&Bs[st][brow*STRD + bcol]);
            const __nv_bfloat16* gB = Bw + (size_t)brow*HDIM + k0 + bcol;
            cpa16(sB, gB); cpa16(sB+16, gB+8);
            asm volatile("cp.async.commit_group;");
        }
        int st = it & 1;
        unsigned aBase = smem_u32(&As[st][(wm*16 + (lane & 15))*STRD + (lane >> 4)*8]);
        unsigned bBase = smem_u32(&Bs[st][(wn*32 + ((lane >> 4) << 3) + (lane & 7))*STRD
                                          + (((lane >> 3) & 1) << 3)]);
        #pragma unroll
        for (int ks = 0; ks < KC; ks += 16) {
            unsigned a0,a1,a2,a3;
            asm volatile("ldmatrix.sync.aligned.m8n8.x4.shared.b16 {%0,%1,%2,%3},[%4];"
                : "=r"(a0),"=r"(a1),"=r"(a2),"=r"(a3) : "r"(aBase + (unsigned)(ks*2)));
            #pragma unroll
            for (int p2 = 0; p2 < 2; p2++) {
                unsigned b0,b1,b2,b3;
                asm volatile("ldmatrix.sync.aligned.m8n8.x4.shared.b16 {%0,%1,%2,%3},[%4];"
                    : "=r"(b0),"=r"(b1),"=r"(b2),"=r"(b3)
                    : "r"(bBase + (unsigned)((p2*16*STRD + ks) * 2)));
                float* c0 = acc[p2*2];
                asm volatile("mma.sync.aligned.m16n8k16.row.col.f32.bf16.bf16.f32 "
                    "{%0,%1,%2,%3},{%4,%5,%6,%7},{%8,%9},{%0,%1,%2,%3};"
                    : "+f"(c0[0]),"+f"(c0[1]),"+f"(c0[2]),"+f"(c0[3])
                    : "r"(a0),"r"(a1),"r"(a2),"r"(a3),"r"(b0),"r"(b1));
                float* c1 = acc[p2*2+1];
                asm volatile("mma.sync.aligned.m16n8k16.row.col.f32.bf16.bf16.f32 "
                    "{%0,%1,%2,%3},{%4,%5,%6,%7},{%8,%9},{%0,%1,%2,%3};"
                    : "+f"(c1[0]),"+f"(c1[1]),"+f"(c1[2]),"+f"(c1[3])
                    : "r"(a0),"r"(a1),"r"(a2),"r"(a3),"r"(b2),"r"(b3));
            }
        }
        __syncthreads();
    }

    int r1 = r0 + wm*16 + (lane >> 2);
    int r2 = r1 + 8;
    #pragma unroll
    for (int p = 0; p < 4; p++) {
        int o = o0 + wn*32 + p*8 + (lane & 3)*2;
        float2 bo = *(const float2*)(bt + o);
        float2 v1; v1.x = acc[p][0] + bo.x; v1.y = acc[p][1] + bo.y;
        float2 v2; v2.x = acc[p][2] + bo.x; v2.y = acc[p][3] + bo.y;
        *(float2*)(g_nm + (size_t)r1*HDIM + o) = v1;
        *(float2*)(g_nm + (size_t)r2*HDIM + o) = v2;
    }
}

// ===== fused edge GEMM over symmetric pairs (layers 1..4), 2-stage ==========
__global__ __launch_bounds__(256) void gemm_pairs_kernel(
    int t, const float* __restrict__ ebt, int src, int dst)
{
    __shared__ __nv_bfloat16 As[2][64*STRD];
    __shared__ __nv_bfloat16 Bs[2][128*STRD];

    int tid  = threadIdx.x;
    int wid  = tid >> 5, lane = tid & 31;
    int wm   = wid & 3, wn = wid >> 2;
    int b    = blockIdx.z;
    int r0   = blockIdx.y * 64;
    int o0   = blockIdx.x * 128;

    const __nv_bfloat16* A  = g_ebuf[src] + ((size_t)b * NPPAD + r0) * HDIM;
    const __nv_bfloat16* Bw = g_eW16 + (size_t)t * HDIM * HDIM + (size_t)o0 * HDIM;

    float acc[8][4] = {};

    int arow = tid >> 2, acol = (tid & 3) * 8;
    int brow = tid >> 1, bcol = (tid & 1) * 16;

    {
        cpa16(smem_u32(&As[0][arow*STRD + acol]), A + (size_t)arow*HDIM + acol);
        unsigned sB = smem_u32(&Bs[0][brow*STRD + bcol]);
        const __nv_bfloat16* gB = Bw + (size_t)brow*HDIM + bcol;
        cpa16(sB, gB); cpa16(sB+16, gB+8);
        asm volatile("cp.async.commit_group;");
    }

    for (int it = 0; it < NIT; it++) {
        asm volatile("cp.async.wait_group 0;");
        __syncthreads();
        if (it + 1 < NIT) {
            int st = (it + 1) & 1;
            int k0 = (it + 1) * KC;
            cpa16(smem_u32(&As[st][arow*STRD + acol]), A + (size_t)arow*HDIM + k0 + acol);
            unsigned sB = smem_u32(&Bs[st][brow*STRD + bcol]);
            const __nv_bfloat16* gB = Bw + (size_t)brow*HDIM + k0 + bcol;
            cpa16(sB, gB); cpa16(sB+16, gB+8);
            asm volatile("cp.async.commit_group;");
        }
        int st = it & 1;
        unsigned aBase = smem_u32(&As[st][(wm*16 + (lane & 15))*STRD + (lane >> 4)*8]);
        unsigned bBase = smem_u32(&Bs[st][(wn*64 + ((lane >> 4) << 3) + (lane & 7))*STRD
                                          + (((lane >> 3) & 1) << 3)]);
        #pragma unroll
        for (int ks = 0; ks < KC; ks += 16) {
            unsigned a0,a1,a2,a3;
            asm volatile("ldmatrix.sync.aligned.m8n8.x4.shared.b16 {%0,%1,%2,%3},[%4];"
                : "=r"(a0),"=r"(a1),"=r"(a2),"=r"(a3) : "r"(aBase + (unsigned)(ks*2)));
            #pragma unroll
            for (int p2 = 0; p2 < 4; p2++) {
                unsigned b0,b1,b2,b3;
                asm volatile("ldmatrix.sync.aligned.m8n8.x4.shared.b16 {%0,%1,%2,%3},[%4];"
                    : "=r"(b0),"=r"(b1),"=r"(b2),"=r"(b3)
                    : "r"(bBase + (unsigned)((p2*16*STRD + ks) * 2)));
                float* c0 = acc[p2*2];
                asm volatile("mma.sync.aligned.m16n8k16.row.col.f32.bf16.bf16.f32 "
                    "{%0,%1,%2,%3},{%4,%5,%6,%7},{%8,%9},{%0,%1,%2,%3};"
                    : "+f"(c0[0]),"+f"(c0[1]),"+f"(c0[2]),"+f"(c0[3])
                    : "r"(a0),"r"(a1),"r"(a2),"r"(a3),"r"(b0),"r"(b1));
                float* c1 = acc[p2*2+1];
                asm volatile("mma.sync.aligned.m16n8k16.row.col.f32.bf16.bf16.f32 "
                    "{%0,%1,%2,%3},{%4,%5,%6,%7},{%8,%9},{%0,%1,%2,%3};"
                    : "+f"(c1[0]),"+f"(c1[1]),"+f"(c1[2]),"+f"(c1[3])
                    : "r"(a0),"r"(a1),"r"(a2),"r"(a3),"r"(b2),"r"(b3));
            }
        }
        __syncthreads();
    }

    // ---- epilogue: leaky + pair-compact bf16 write ----
    int rbase = wm*16 + (lane >> 2);
    int r1 = rbase, r2 = rbase + 8;
    ushort2 pj1 = g_pt[r0 + r1];
    ushort2 pj2 = g_pt[r0 + r2];
    const float* nmb = g_nm + (size_t)b * NROI * HDIM;
    __nv_bfloat16* d1 = g_ebuf[dst] + ((size_t)b * NPPAD + r0 + r1) * HDIM;
    __nv_bfloat16* d2 = g_ebuf[dst] + ((size_t)b * NPPAD + r0 + r2) * HDIM;

    #pragma unroll
    for (int p = 0; p < 8; p++) {
        int o = o0 + wn*64 + p*8 + (lane & 3)*2;
        float2 ebv = *(const float2*)(ebt + o);
        float2 i1 = *(const float2*)(nmb + (size_t)pj1.x*HDIM + o);
        float2 j1 = *(const float2*)(nmb + (size_t)pj1.y*HDIM + o);
        float2 i2 = *(const float2*)(nmb + (size_t)pj2.x*HDIM + o);
        float2 j2 = *(const float2*)(nmb + (size_t)pj2.y*HDIM + o);
        float e00 = leaky(acc[p][0] + i1.x + j1.x + ebv.x);
        float e01 = leaky(acc[p][1] + i1.y + j1.y + ebv.y);
        float e10 = leaky(acc[p][2] + i2.x + j2.x + ebv.x);
        float e11 = leaky(acc[p][3] + i2.y + j2.y + ebv.y);
        *(__nv_bfloat162*)(d1 + o) = __floats2bfloat162_rn(e00, e01);
        *(__nv_bfloat162*)(d2 + o) = __floats2bfloat162_rn(e10, e11);
    }
}

// ---------------- output: concat broadcast of node_state --------------------
__global__ void out_kernel(float* __restrict__ out) {
    size_t f = (size_t)blockIdx.x * blockDim.x + threadIdx.x;
    size_t total4 = (size_t)BSZ*NROI*NROI*1024 / 4;
    if (f >= total4) return;
    size_t flat = f * 4;
    int c = (int)(flat & 1023);
    size_t bij = flat >> 10;
    int j = (int)(bij & 63);
    size_t bi = bij >> 6;            // b*64+i
    size_t b  = bi >> 6;
    const float* src = (c < 512)
        ? (g_ns + bi * HDIM + c)
        : (g_ns + (b*64 + j) * HDIM + (c - 512));
    __stcs((float4*)(out + flat), *(const float4*)src);
}

// ---------------- host launch ------------------------------------------------
extern "C" void kernel_launch(void* const* d_in, const int* in_sizes, int n_in,
                              void* d_out, int out_size) {
    const float* roi = (const float*)d_in[0];
    const float* img = (const float*)d_in[1];
    const float* nW  = (const float*)d_in[2];
    const float* nb  = (const float*)d_in[3];
    const float* eW  = (const float*)d_in[4];
    const float* eb  = (const float*)d_in[5];
    const int*   msk = (const int*)d_in[6];
    float* out = (float*)d_out;

    prep_kernel<<<2048, 256>>>(roi, img, msk, eW, nW);

    for (int t = 0; t < NLAYER; t++) {
        nm_mma_kernel<<<dim3(8, 16), 128>>>(t, nb + (size_t)t*HDIM);
        if (t == 0) {
            em0_kernel<<<512, 256>>>(eW, eb);
            edge0_fused_kernel<<<dim3(2, 512), 256>>>(msk);
        } else {
            int dst = t & 1;
            int src = dst ^ 1;
            gemm_pairs_kernel<<<dim3(4, 33, 8), 256>>>(
                t, eb + (size_t)t*HDIM, src, dst);
            agg_node_kernel<<<dim3(2, 512), 256>>>(dst, msk);
        }
    }

    out_kernel<<<32768, 256>>>(out);
}